// round 15
// baseline (speedup 1.0000x reference)
#include <cuda_runtime.h>
#include <cuda_fp16.h>
#include <cstdint>

#define BB 32
#define CC 16
#define NN 64
#define TL 4096
#define OO 16
#define TT 128   // t-tile per CTA

// Channel-summed x: xsum[b][n][t], 33.5 MB -> L2-resident between A and B.
__device__ __align__(16) float g_xsum[(size_t)BB * NN * TL];

// B operand of every mma, precomputed in fp16 fragment-register layout:
// g_Bfrag[((o*8 + nt)*4 + ks)*32 + lane] = {b0, b1}  (fp16x2 each)
// (nt, ks) tile the 64x64 M_o into n-tiles of 8 (i) and k-steps of 16 (j);
// b0 holds k = ks*16 + tig*2 + {0,1}, b1 holds k = ks*16 + tig*2 + {8,9},
// n = nt*8 + gid (gid = lane>>2, tig = lane&3), low 16 bits = lower k.
// 128 KB total, L1/L2-resident, broadcast across all warps/CTAs.
__device__ __align__(16) uint2 g_Bfrag[OO * 8 * 4 * 32];

// ---------------------------------------------------------------------------
// Second-stream plumbing (static-init; proven to graph-capture in R11/R12).
// compute_B runs concurrently with channel_sum; kernel B waits on its event.
// ---------------------------------------------------------------------------
struct GraphStreams {
    cudaStream_t s2;
    cudaEvent_t fork, done;
    GraphStreams() {
        cudaStreamCreateWithFlags(&s2, cudaStreamNonBlocking);
        cudaEventCreateWithFlags(&fork, cudaEventDisableTiming);
        cudaEventCreateWithFlags(&done, cudaEventDisableTiming);
    }
};
static GraphStreams g_gs;

// ---------------------------------------------------------------------------
// Kernel 1: precompute M in fp16 fragment layout (smem-staged U/theta).
// M[o][j][i] = sum_n U[i,n] * theta[n,o] * U[j,n]
// fp16 rounding of M bounds the kernel's error at ~2^-12 relative.
// ---------------------------------------------------------------------------
__global__ void compute_B_kernel(const float* __restrict__ U,
                                 const float* __restrict__ theta) {
    __shared__ float sU[64 * 64];    // 16 KB
    __shared__ float sT[64 * 16];    // 4 KB
    int t = threadIdx.x;
    for (int i = t; i < 4096; i += 256) sU[i] = U[i];
    for (int i = t; i < 1024; i += 256) sT[i] = theta[i];
    __syncthreads();

    int idx  = blockIdx.x * 256 + t;            // 0..16383
    int lane = idx & 31;
    int ks   = (idx >> 5) & 3;
    int nt   = (idx >> 7) & 7;
    int o    = idx >> 10;
    int gid  = lane >> 2, tig = lane & 3;
    int n    = nt * 8 + gid;            // i
    int kb   = ks * 16 + tig * 2;       // base j

    int j0 = kb, j1 = kb + 1, j2 = kb + 8, j3 = kb + 9;
    float a0 = 0.f, a1 = 0.f, a2 = 0.f, a3 = 0.f;
#pragma unroll
    for (int q = 0; q < 64; ++q) {
        float un = sU[n * 64 + q] * sT[q * 16 + o];
        a0 += un * sU[j0 * 64 + q];
        a1 += un * sU[j1 * 64 + q];
        a2 += un * sU[j2 * 64 + q];
        a3 += un * sU[j3 * 64 + q];
    }
    __half2 h0 = __floats2half2_rn(a0, a1);  // .x = low k
    __half2 h1 = __floats2half2_rn(a2, a3);
    uint2 v;
    v.x = *(unsigned*)&h0;
    v.y = *(unsigned*)&h1;
    g_Bfrag[idx] = v;
}

// ---------------------------------------------------------------------------
// Kernel A: streaming channel sum (measured 79.6us @ 86% DRAM — roofline).
// ---------------------------------------------------------------------------
__global__ void __launch_bounds__(256)
channel_sum_kernel(const float* __restrict__ x) {
    int gid = blockIdx.x * 256 + threadIdx.x;        // 0 .. BB*NN*TL/4 - 1
    int b   = gid / (NN * (TL / 4));
    int rem = gid - b * (NN * (TL / 4));             // n*(TL/4) + tc
    const float4* px = (const float4*)x +
                       (size_t)b * CC * NN * (TL / 4) + rem;
    float4 s = make_float4(0.f, 0.f, 0.f, 0.f);
#pragma unroll
    for (int c = 0; c < CC; ++c) {
        float4 v = __ldcs(px + (size_t)c * (NN * (TL / 4)));
        s.x += v.x; s.y += v.y; s.z += v.z; s.w += v.w;
    }
    ((float4*)g_xsum)[gid] = s;    // default policy: L2-resident
}

// ---------------------------------------------------------------------------
// mma.sync m16n8k16 fp16 (baseline PTX, assembles under compute_103)
// ---------------------------------------------------------------------------
__device__ __forceinline__ void mma16816(float* c, const unsigned* a,
                                         unsigned b0, unsigned b1) {
    asm volatile(
        "mma.sync.aligned.m16n8k16.row.col.f32.f16.f16.f32 "
        "{%0,%1,%2,%3}, {%4,%5,%6,%7}, {%8,%9}, {%0,%1,%2,%3};"
        : "+f"(c[0]), "+f"(c[1]), "+f"(c[2]), "+f"(c[3])
        : "r"(a[0]), "r"(a[1]), "r"(a[2]), "r"(a[3]), "r"(b0), "r"(b1));
}

// ---------------------------------------------------------------------------
// Kernel B: per CTA = (b, 128-t tile), 128 threads (4 warps), 5 CTAs/SM.
//  Phase 1: copy xsum tile (32 KB, L2-resident) -> smem.
//  Phase 2: per-warp A fragments for TWO 16-row m-tiles, fp16 hi/lo (64 regs),
//           reused for all 16 o.
//  Phase 3: per o, nt=0..7 with ping-pong-prefetched fp16 B frags (LDG.64,
//           L1-resident), 16 mmas per nt (2-term: A_hi*B + A_lo*B),
//           streaming stores. Zero LDS in the hot loop.
// ---------------------------------------------------------------------------
#define PITCH 132

__global__ void __launch_bounds__(128, 5)
spectral_hmma_kernel(float* __restrict__ y) {
    __shared__ float xs[NN * PITCH];   // 33792 B

    const int tid  = threadIdx.x;
    const int wid  = tid >> 5;
    const int lane = tid & 31;
    const int gid  = lane >> 2;
    const int tig  = lane & 3;
    const int b    = blockIdx.y;
    const int t0   = blockIdx.x * TT;

    // ---- Phase 1: xsum tile (L2) -> smem
    const float4* xsrc = (const float4*)g_xsum +
                         (size_t)b * NN * (TL / 4) + t0 / 4;
#pragma unroll
    for (int k = 0; k < 16; ++k) {
        int eid = tid + k * 128;            // 0..2047 float4 elements
        int j   = eid >> 5;
        int tc  = eid & 31;                 // float4 column 0..31
        float4 v = __ldcg(xsrc + (size_t)j * (TL / 4) + tc);
        *(float4*)&xs[j * PITCH + tc * 4] = v;
    }
    __syncthreads();

    // ---- Phase 2: A fragments, 2 m-tiles per warp (t rows wid*32 .. +31),
    //      fp16 hi + fp16 residual lo (2-term split; A error ~2^-22)
    unsigned Ahi[2][4][4], Alo[2][4][4];
    {
        const int tb = wid * 32;
#pragma unroll
        for (int mt = 0; mt < 2; ++mt) {
#pragma unroll
            for (int ks = 0; ks < 4; ++ks) {
                int j0 = ks * 16 + tig * 2;
                int r0 = tb + mt * 16 + gid;
#pragma unroll
                for (int p = 0; p < 4; ++p) {
                    // p: 0->(r0,j0) 1->(r0+8,j0) 2->(r0,j0+8) 3->(r0+8,j0+8)
                    int rr = r0 + (p & 1) * 8;
                    int jj = j0 + (p >> 1) * 8;
                    float f0 = xs[jj * PITCH + rr];
                    float f1 = xs[(jj + 1) * PITCH + rr];
                    __half2 h = __floats2half2_rn(f0, f1);
                    float q0 = f0 - __half2float(__low2half(h));
                    float q1 = f1 - __half2float(__high2half(h));
                    __half2 l = __floats2half2_rn(q0, q1);
                    Ahi[mt][ks][p] = *(unsigned*)&h;
                    Alo[mt][ks][p] = *(unsigned*)&l;
                }
            }
        }
    }

    // ---- Phase 3: per-o GEMM + streaming store
    for (int o = 0; o < OO; ++o) {
        const uint2* bp = g_Bfrag + (size_t)o * (8 * 4 * 32) + lane;
        float* const yo = y + ((size_t)b * OO + o) * NN * TL + t0;

        uint2 bfA[4], bfB[4];
#pragma unroll
        for (int ks = 0; ks < 4; ++ks) bfA[ks] = bp[ks * 32];   // nt = 0

#pragma unroll
        for (int nt = 0; nt < 8; ++nt) {
            const uint2* cur = (nt & 1) ? bfB : bfA;
            uint2*       nxt = (nt & 1) ? bfA : bfB;
            if (nt < 7) {
#pragma unroll
                for (int ks = 0; ks < 4; ++ks)
                    nxt[ks] = bp[((nt + 1) * 4 + ks) * 32];
            }

            float acc[2][4] = {{0.f, 0.f, 0.f, 0.f}, {0.f, 0.f, 0.f, 0.f}};
#pragma unroll
            for (int ks = 0; ks < 4; ++ks) {
#pragma unroll
                for (int mt = 0; mt < 2; ++mt) {
                    mma16816(acc[mt], Ahi[mt][ks], cur[ks].x, cur[ks].y); // hi*B
                    mma16816(acc[mt], Alo[mt][ks], cur[ks].x, cur[ks].y); // lo*B
                }
            }

            // c0 -> (i0, t), c1 -> (i0+1, t), c2 -> (i0, t+8), c3 -> (i0+1, t+8)
            int i0 = nt * 8 + tig * 2;
#pragma unroll
            for (int mt = 0; mt < 2; ++mt) {
                int tr = wid * 32 + mt * 16 + gid;
                float* yb = yo + (size_t)i0 * TL + tr;
                __stcs(yb,          acc[mt][0]);
                __stcs(yb + TL,     acc[mt][1]);
                __stcs(yb + 8,      acc[mt][2]);
                __stcs(yb + TL + 8, acc[mt][3]);
            }
        }
    }
}

// ---------------------------------------------------------------------------
// kernel_launch: graph-capturable, allocation-free. compute_B overlaps
// channel_sum on a second stream; kernel B is gated on both.
// Inputs: x (B,C,N,T) f32, U (N,N) f32, theta (N,OUT) f32. Output y f32.
// ---------------------------------------------------------------------------
extern "C" void kernel_launch(void* const* d_in, const int* in_sizes, int n_in,
                              void* d_out, int out_size) {
    const float* x     = (const float*)d_in[0];
    const float* U     = (const float*)d_in[1];
    const float* theta = (const float*)d_in[2];
    float* y = (float*)d_out;

    // fork: s2 inherits prior main-stream dependencies
    cudaEventRecord(g_gs.fork, 0);
    cudaStreamWaitEvent(g_gs.s2, g_gs.fork, 0);

    // s2: B-fragment table (4us) overlaps A's 80us stream
    compute_B_kernel<<<64, 256, 0, g_gs.s2>>>(U, theta);
    cudaEventRecord(g_gs.done, g_gs.s2);

    // main stream: channel sum, then B gated on compute_B too
    channel_sum_kernel<<<(BB * NN * TL / 4) / 256, 256>>>(x);
    cudaStreamWaitEvent(0, g_gs.done, 0);
    spectral_hmma_kernel<<<dim3(TL / TT, BB), 128>>>(y);
}

// round 16
// speedup vs baseline: 1.1141x; 1.1141x over previous
#include <cuda_runtime.h>
#include <cuda_fp16.h>
#include <cstdint>

#define BB 32
#define CC 16
#define NN 64
#define TL 4096
#define OO 16
#define TT 128   // t-tile per CTA

// Channel-summed x: xsum[b][n][t], 33.5 MB -> L2-resident between A and B.
__device__ __align__(16) float g_xsum[(size_t)BB * NN * TL];

// B operand of every mma, precomputed in fp16 fragment-register layout:
// g_Bfrag[((o*8 + nt)*4 + ks)*32 + lane] = {b0, b1}  (fp16x2 each)
// (nt, ks) tile the 64x64 M_o into n-tiles of 8 (i) and k-steps of 16 (j);
// b0 holds k = ks*16 + tig*2 + {0,1}, b1 holds k = ks*16 + tig*2 + {8,9},
// n = nt*8 + gid (gid = lane>>2, tig = lane&3), low 16 bits = lower k.
// 128 KB total, L1/L2-resident, broadcast across all warps/CTAs.
__device__ __align__(16) uint2 g_Bfrag[OO * 8 * 4 * 32];

// ---------------------------------------------------------------------------
// Kernel 1: precompute M in fp16 fragment layout (smem-staged U/theta).
// M[o][j][i] = sum_n U[i,n] * theta[n,o] * U[j,n]
// fp16 rounding of M contributes ~2e-4 relative error (measured in R13).
// ---------------------------------------------------------------------------
__global__ void compute_B_kernel(const float* __restrict__ U,
                                 const float* __restrict__ theta) {
    __shared__ float sU[64 * 64];    // 16 KB
    __shared__ float sT[64 * 16];    // 4 KB
    int t = threadIdx.x;
    for (int i = t; i < 4096; i += 256) sU[i] = U[i];
    for (int i = t; i < 1024; i += 256) sT[i] = theta[i];
    __syncthreads();

    int idx  = blockIdx.x * 256 + t;            // 0..16383
    int lane = idx & 31;
    int ks   = (idx >> 5) & 3;
    int nt   = (idx >> 7) & 7;
    int o    = idx >> 10;
    int gid  = lane >> 2, tig = lane & 3;
    int n    = nt * 8 + gid;            // i
    int kb   = ks * 16 + tig * 2;       // base j

    int j0 = kb, j1 = kb + 1, j2 = kb + 8, j3 = kb + 9;
    float a0 = 0.f, a1 = 0.f, a2 = 0.f, a3 = 0.f;
#pragma unroll
    for (int q = 0; q < 64; ++q) {
        float un = sU[n * 64 + q] * sT[q * 16 + o];
        a0 += un * sU[j0 * 64 + q];
        a1 += un * sU[j1 * 64 + q];
        a2 += un * sU[j2 * 64 + q];
        a3 += un * sU[j3 * 64 + q];
    }
    __half2 h0 = __floats2half2_rn(a0, a1);  // .x = low k
    __half2 h1 = __floats2half2_rn(a2, a3);
    uint2 v;
    v.x = *(unsigned*)&h0;
    v.y = *(unsigned*)&h1;
    g_Bfrag[idx] = v;
}

// ---------------------------------------------------------------------------
// Kernel A: streaming channel sum (measured 79.6us @ 86% DRAM — roofline).
// ---------------------------------------------------------------------------
__global__ void __launch_bounds__(256)
channel_sum_kernel(const float* __restrict__ x) {
    int gid = blockIdx.x * 256 + threadIdx.x;        // 0 .. BB*NN*TL/4 - 1
    int b   = gid / (NN * (TL / 4));
    int rem = gid - b * (NN * (TL / 4));             // n*(TL/4) + tc
    const float4* px = (const float4*)x +
                       (size_t)b * CC * NN * (TL / 4) + rem;
    float4 s = make_float4(0.f, 0.f, 0.f, 0.f);
#pragma unroll
    for (int c = 0; c < CC; ++c) {
        float4 v = __ldcs(px + (size_t)c * (NN * (TL / 4)));
        s.x += v.x; s.y += v.y; s.z += v.z; s.w += v.w;
    }
    ((float4*)g_xsum)[gid] = s;    // default policy: L2-resident
}

// ---------------------------------------------------------------------------
// mma.sync m16n8k16 fp16 (baseline PTX, assembles under compute_103)
// ---------------------------------------------------------------------------
__device__ __forceinline__ void mma16816(float* c, const unsigned* a,
                                         unsigned b0, unsigned b1) {
    asm volatile(
        "mma.sync.aligned.m16n8k16.row.col.f32.f16.f16.f32 "
        "{%0,%1,%2,%3}, {%4,%5,%6,%7}, {%8,%9}, {%0,%1,%2,%3};"
        : "+f"(c[0]), "+f"(c[1]), "+f"(c[2]), "+f"(c[3])
        : "r"(a[0]), "r"(a[1]), "r"(a[2]), "r"(a[3]), "r"(b0), "r"(b1));
}

// ---------------------------------------------------------------------------
// Kernel B: per CTA = (b, 128-t tile), 128 threads (4 warps), 5 CTAs/SM.
//  Phase 1: copy xsum tile (32 KB, L2-resident) -> smem.
//  Phase 2: per-warp A fragments for TWO 16-row m-tiles, SINGLE fp16
//           (32 regs; A-rounding ~2e-4, same order as M's — error budget
//           allows it), reused for all 16 o.
//  Phase 3: per o, nt=0..7 with ping-pong-prefetched fp16 B frags (LDG.64,
//           L1-resident), 8 mmas per nt (single term A*B), streaming stores.
//           Zero LDS in the hot loop. Natural regs ~80 -> occ 5 without spills.
// ---------------------------------------------------------------------------
#define PITCH 132

__global__ void __launch_bounds__(128, 5)
spectral_hmma_kernel(float* __restrict__ y) {
    __shared__ float xs[NN * PITCH];   // 33792 B

    const int tid  = threadIdx.x;
    const int wid  = tid >> 5;
    const int lane = tid & 31;
    const int gid  = lane >> 2;
    const int tig  = lane & 3;
    const int b    = blockIdx.y;
    const int t0   = blockIdx.x * TT;

    // ---- Phase 1: xsum tile (L2) -> smem
    const float4* xsrc = (const float4*)g_xsum +
                         (size_t)b * NN * (TL / 4) + t0 / 4;
#pragma unroll
    for (int k = 0; k < 16; ++k) {
        int eid = tid + k * 128;            // 0..2047 float4 elements
        int j   = eid >> 5;
        int tc  = eid & 31;                 // float4 column 0..31
        float4 v = __ldcg(xsrc + (size_t)j * (TL / 4) + tc);
        *(float4*)&xs[j * PITCH + tc * 4] = v;
    }
    __syncthreads();

    // ---- Phase 2: A fragments, 2 m-tiles per warp (t rows wid*32 .. +31),
    //      single fp16 (32 regs)
    unsigned Ahi[2][4][4];
    {
        const int tb = wid * 32;
#pragma unroll
        for (int mt = 0; mt < 2; ++mt) {
#pragma unroll
            for (int ks = 0; ks < 4; ++ks) {
                int j0 = ks * 16 + tig * 2;
                int r0 = tb + mt * 16 + gid;
#pragma unroll
                for (int p = 0; p < 4; ++p) {
                    // p: 0->(r0,j0) 1->(r0+8,j0) 2->(r0,j0+8) 3->(r0+8,j0+8)
                    int rr = r0 + (p & 1) * 8;
                    int jj = j0 + (p >> 1) * 8;
                    float f0 = xs[jj * PITCH + rr];
                    float f1 = xs[(jj + 1) * PITCH + rr];
                    __half2 h = __floats2half2_rn(f0, f1);
                    Ahi[mt][ks][p] = *(unsigned*)&h;
                }
            }
        }
    }

    // ---- Phase 3: per-o GEMM + streaming store
    for (int o = 0; o < OO; ++o) {
        const uint2* bp = g_Bfrag + (size_t)o * (8 * 4 * 32) + lane;
        float* const yo = y + ((size_t)b * OO + o) * NN * TL + t0;

        uint2 bfA[4], bfB[4];
#pragma unroll
        for (int ks = 0; ks < 4; ++ks) bfA[ks] = bp[ks * 32];   // nt = 0

#pragma unroll
        for (int nt = 0; nt < 8; ++nt) {
            const uint2* cur = (nt & 1) ? bfB : bfA;
            uint2*       nxt = (nt & 1) ? bfA : bfB;
            if (nt < 7) {
#pragma unroll
                for (int ks = 0; ks < 4; ++ks)
                    nxt[ks] = bp[((nt + 1) * 4 + ks) * 32];
            }

            float acc[2][4] = {{0.f, 0.f, 0.f, 0.f}, {0.f, 0.f, 0.f, 0.f}};
#pragma unroll
            for (int ks = 0; ks < 4; ++ks) {
#pragma unroll
                for (int mt = 0; mt < 2; ++mt) {
                    mma16816(acc[mt], Ahi[mt][ks], cur[ks].x, cur[ks].y);
                }
            }

            // c0 -> (i0, t), c1 -> (i0+1, t), c2 -> (i0, t+8), c3 -> (i0+1, t+8)
            int i0 = nt * 8 + tig * 2;
#pragma unroll
            for (int mt = 0; mt < 2; ++mt) {
                int tr = wid * 32 + mt * 16 + gid;
                float* yb = yo + (size_t)i0 * TL + tr;
                __stcs(yb,          acc[mt][0]);
                __stcs(yb + TL,     acc[mt][1]);
                __stcs(yb + 8,      acc[mt][2]);
                __stcs(yb + TL + 8, acc[mt][3]);
            }
        }
    }
}

// ---------------------------------------------------------------------------
// kernel_launch: graph-capturable, allocation-free, single stream (serial
// split — measured A=79.6us @86% DRAM; stream-overlap variants regressed).
// Inputs: x (B,C,N,T) f32, U (N,N) f32, theta (N,OUT) f32. Output y f32.
// ---------------------------------------------------------------------------
extern "C" void kernel_launch(void* const* d_in, const int* in_sizes, int n_in,
                              void* d_out, int out_size) {
    const float* x     = (const float*)d_in[0];
    const float* U     = (const float*)d_in[1];
    const float* theta = (const float*)d_in[2];
    float* y = (float*)d_out;

    channel_sum_kernel<<<(BB * NN * TL / 4) / 256, 256>>>(x);
    compute_B_kernel<<<64, 256>>>(U, theta);
    spectral_hmma_kernel<<<dim3(TL / TT, BB), 128>>>(y);
}